// round 15
// baseline (speedup 1.0000x reference)
#include <cuda_runtime.h>
#include <cuda_bf16.h>
#include <math.h>
#include <stdint.h>

#define B_  64
#define E_  512
#define H_  512
#define V_  32000
#define T_  32
#define G4  2048   // 4*H
#define NB  282u   // total blocks per k_step launch

typedef unsigned long long ull;

// ---------------- persistent device state ----------------
__device__ __align__(16) float g_c[B_ * H_];        // cell state
__device__ __align__(16) float g_gates[4][B_ * G4]; // planes: ih-k0, ih-k1, hh-k0, hh-k1
__device__ ull g_amax[2][B_];                       // packed argmax accumulators
__device__ unsigned g_ctr;                          // monotonic barrier ticket counter
// bf16 2-term splits
__device__ __align__(16) __nv_bfloat16 g_Wb1[(size_t)V_ * 512];   // lin_W hi
__device__ __align__(16) __nv_bfloat16 g_Wb2[(size_t)V_ * 512];   // lin_W lo
__device__ __align__(16) __nv_bfloat16 g_Ib1[2048 * 512];         // W_ih hi
__device__ __align__(16) __nv_bfloat16 g_Ib2[2048 * 512];         // W_ih lo
__device__ __align__(16) __nv_bfloat16 g_Hb1[2048 * 512];         // W_hh hi
__device__ __align__(16) __nv_bfloat16 g_Hb2[2048 * 512];         // W_hh lo
__device__ __align__(16) __nv_bfloat16 g_hb[2][B_ * 512];         // h(t) splits [term][b*512+k]

__device__ __forceinline__ unsigned fkey(float f) {
    unsigned u = __float_as_uint(f);
    return (u & 0x80000000u) ? ~u : (u | 0x80000000u);
}
__device__ __forceinline__ uint32_t smem_u32(const void* p) {
    uint32_t a;
    asm("{ .reg .u64 t; cvta.to.shared.u64 t, %1; cvt.u32.u64 %0, t; }" : "=r"(a) : "l"(p));
    return a;
}
__device__ __forceinline__ void ldsm4(uint32_t* r, uint32_t addr) {
    asm volatile("ldmatrix.sync.aligned.m8n8.x4.shared.b16 {%0,%1,%2,%3}, [%4];"
        : "=r"(r[0]), "=r"(r[1]), "=r"(r[2]), "=r"(r[3]) : "r"(addr));
}
__device__ __forceinline__ void mma16816(float* d, const uint32_t* a, uint32_t b0, uint32_t b1) {
    asm volatile("mma.sync.aligned.m16n8k16.row.col.f32.bf16.bf16.f32 "
        "{%0,%1,%2,%3}, {%4,%5,%6,%7}, {%8,%9}, {%0,%1,%2,%3};"
        : "+f"(d[0]), "+f"(d[1]), "+f"(d[2]), "+f"(d[3])
        : "r"(a[0]), "r"(a[1]), "r"(a[2]), "r"(a[3]), "r"(b0), "r"(b1));
}
__device__ __forceinline__ void cpasync16(uint32_t dst, const void* src) {
    asm volatile("cp.async.cg.shared.global [%0], [%1], 16;" :: "r"(dst), "l"(src));
}
#define SW128(o) ((o) ^ (((o) >> 3) & 0x70))

// Dynamic smem layout (per buffer): W1 16K | W2 16K | H1 8K | H2 8K
#define DSM_STRIDE 49152
#define DSM_W1 0
#define DSM_W2 16384
#define DSM_H1 32768
#define DSM_H2 40960
#define DSM_TOT (2 * DSM_STRIDE)

// ---- device-wide barrier: ALL NB blocks arrive; replay-safe (monotonic) ----
__device__ __forceinline__ void bar_all(int tid, unsigned* s_tk) {
    __syncthreads();
    if (tid == 0) *s_tk = atomicAdd(&g_ctr, 1u);
    __syncthreads();
    unsigned target = (*s_tk / NB + 1u) * NB;
    if (tid == 0) {
        unsigned v;
        for (;;) {
            asm volatile("ld.global.cg.u32 %0, [%1];" : "=r"(v) : "l"(&g_ctr));
            if ((int)(v - target) >= 0) break;
            __nanosleep(128);
        }
    }
    __syncthreads();
    __threadfence();
}

// =========================================================
// k_splitall: one prologue kernel producing every bf16 split.
// =========================================================
__global__ __launch_bounds__(256) void k_splitall(
    const float* __restrict__ lin_W, const float* __restrict__ W_ih,
    const float* __restrict__ W_hh,  const float* __restrict__ features)
{
    const int bid = blockIdx.x;
    const int tid = threadIdx.x;
    if (bid < 64000) {
        size_t i = (size_t)bid * 256 + tid;
        float w = lin_W[i];
        __nv_bfloat16 h1 = __float2bfloat16(w);
        g_Wb1[i] = h1;
        g_Wb2[i] = __float2bfloat16(w - __bfloat162float(h1));
    } else if (bid < 68096) {
        int i = (bid - 64000) * 256 + tid;
        float w = W_ih[i];
        __nv_bfloat16 h1 = __float2bfloat16(w);
        g_Ib1[i] = h1;
        g_Ib2[i] = __float2bfloat16(w - __bfloat162float(h1));
    } else if (bid < 72192) {
        int i = (bid - 68096) * 256 + tid;
        float w = W_hh[i];
        __nv_bfloat16 h1 = __float2bfloat16(w);
        g_Hb1[i] = h1;
        g_Hb2[i] = __float2bfloat16(w - __bfloat162float(h1));
    } else {
        int i = (bid - 72192) * 256 + tid;
        float f = features[i];
        __nv_bfloat16 h1 = __float2bfloat16(f);
        g_hb[0][i] = h1;
        g_hb[1][i] = __float2bfloat16(f - __bfloat162float(h1));
    }
}

// ---- hh-gate GEMM body: 128r x 64b x 256k from g_Hb* / g_hb -> plane ----
__device__ void gates_hh(char* dsm, uint32_t sb, int tid, int wid, int lid,
                         int rb, int kbase, int plane)
{
    auto stage = [&](int buf, int c) {
        const int k0 = kbase + c * 64;
        uint32_t base = sb + buf * DSM_STRIDE;
        #pragma unroll
        for (int q = 0; q < 4; q++) {
            int idx = tid + q * 256;
            int r = idx >> 3, uu = idx & 7;
            uint32_t dst = SW128((uint32_t)(r * 128 + uu * 16));
            size_t so = (size_t)(rb + r) * 512 + k0 + uu * 8;
            cpasync16(base + DSM_W1 + dst, g_Hb1 + so);
            cpasync16(base + DSM_W2 + dst, g_Hb2 + so);
        }
        #pragma unroll
        for (int q = 0; q < 2; q++) {
            int idx = tid + q * 256;
            int b = idx >> 3, uu = idx & 7;
            uint32_t dst = SW128((uint32_t)(b * 128 + uu * 16));
            size_t so = (size_t)b * 512 + k0 + uu * 8;
            cpasync16(base + DSM_H1 + dst, g_hb[0] + so);
            cpasync16(base + DSM_H2 + dst, g_hb[1] + so);
        }
        asm volatile("cp.async.commit_group;" ::: "memory");
    };

    const int sel = lid >> 3, row = lid & 7;
    const int aV  = 16 * wid + ((sel & 1) << 3) + row;
    const int aKo = (sel >> 1) << 3;
    const int bB  = ((sel >> 1) << 3) + row;
    const int bKo = (sel & 1) << 3;

    float acc[8][4] = {};
    stage(0, 0);
    for (int c = 0; c < 4; c++) {
        if (c < 3) {
            stage((c + 1) & 1, c + 1);
            asm volatile("cp.async.wait_group 1;" ::: "memory");
        } else {
            asm volatile("cp.async.wait_group 0;" ::: "memory");
        }
        __syncthreads();
        const uint32_t base = sb + (c & 1) * DSM_STRIDE;
        #pragma unroll
        for (int kk = 0; kk < 64; kk += 16) {
            uint32_t a1[4], a2[4];
            uint32_t aoff = SW128((uint32_t)(aV * 128 + (kk + aKo) * 2));
            ldsm4(a1, base + DSM_W1 + aoff);
            ldsm4(a2, base + DSM_W2 + aoff);
            #pragma unroll
            for (int jp = 0; jp < 4; jp++) {
                uint32_t b1[4], b2[4];
                uint32_t boff = SW128((uint32_t)((16 * jp + bB) * 128 + (kk + bKo) * 2));
                ldsm4(b1, base + DSM_H1 + boff);
                ldsm4(b2, base + DSM_H2 + boff);
                mma16816(acc[2 * jp],     a1, b1[0], b1[1]);
                mma16816(acc[2 * jp + 1], a1, b1[2], b1[3]);
                mma16816(acc[2 * jp],     a1, b2[0], b2[1]);
                mma16816(acc[2 * jp + 1], a1, b2[2], b2[3]);
                mma16816(acc[2 * jp],     a2, b1[0], b1[1]);
                mma16816(acc[2 * jp + 1], a2, b1[2], b1[3]);
            }
        }
        __syncthreads();
    }

    float* gp = g_gates[plane];
    const int qrow = lid >> 2, qcol = lid & 3;
    const int r0 = rb + 16 * wid + qrow;
    const int r1 = r0 + 8;
    #pragma unroll
    for (int j = 0; j < 8; j++) {
        int blo = 8 * j + 2 * qcol, bhi = blo + 1;
        gp[(size_t)blo * G4 + r0] = acc[j][0];
        gp[(size_t)bhi * G4 + r0] = acc[j][1];
        gp[(size_t)blo * G4 + r1] = acc[j][2];
        gp[(size_t)bhi * G4 + r1] = acc[j][3];
    }
}

// ---- logits full chunk staging (W + H) ----
__device__ __forceinline__ void stage_chunk(uint32_t sb, int buf, int vb, int k0, int tid)
{
    uint32_t base = sb + buf * DSM_STRIDE;
    #pragma unroll
    for (int q = 0; q < 4; q++) {
        int idx = tid + q * 256;
        int v = idx >> 3, uu = idx & 7;
        uint32_t dst = SW128((uint32_t)(v * 128 + uu * 16));
        size_t so = (size_t)(vb + v) * 512 + k0 + uu * 8;
        cpasync16(base + DSM_W1 + dst, g_Wb1 + so);
        cpasync16(base + DSM_W2 + dst, g_Wb2 + so);
    }
    #pragma unroll
    for (int q = 0; q < 2; q++) {
        int idx = tid + q * 256;
        int b = idx >> 3, uu = idx & 7;
        uint32_t dst = SW128((uint32_t)(b * 128 + uu * 16));
        size_t so = (size_t)b * 512 + k0 + uu * 8;
        cpasync16(base + DSM_H1 + dst, g_hb[0] + so);
        cpasync16(base + DSM_H2 + dst, g_hb[1] + so);
    }
    asm volatile("cp.async.commit_group;" ::: "memory");
}

// =========================================================
// k_step: ONE launch per timestep.
//  bids 0..249   : logits (128v x 64b x 512k) — pre-stage W c0, wait barriers.
//  bids 250..281 : ih gates -> barA -> fused LSTM update -> barB -> hh gates(t+1).
//  t<0: only gate bids run (hh from features splits); no barriers.
// =========================================================
__global__ __launch_bounds__(256, 2) void k_step(
    int t, const void* __restrict__ captions, const float* __restrict__ embed,
    const float* __restrict__ features,
    const float* __restrict__ b_ih, const float* __restrict__ b_hh,
    const float* __restrict__ lin_b, float* __restrict__ out)
{
    extern __shared__ char dsm[];
    __shared__ ull s_amax[64];
    __shared__ int stok[B_];
    __shared__ unsigned s_tk;
    const uint32_t sb = smem_u32(dsm);
    const int tid = threadIdx.x;
    const int bid = blockIdx.x;
    const int wid = tid >> 5, lid = tid & 31;

    if (bid >= 250) {
        // ================= gate block =================
        const int gid   = bid - 250;
        const int rb    = (gid >> 1) * 128;
        const int kbase = (gid & 1) * 256;

        if (t < 0) {                  // prologue: hh gates for t=0 from features splits
            gates_hh(dsm, sb, tid, wid, lid, rb, kbase, 2 + (gid & 1));
            return;
        }

        // ---- token resolution ----
        if (t == 0 && gid == 0 && tid < 128)
            g_amax[tid >> 6][tid & 63] = 0ull;
        if (tid < B_) {
            int tok;
            if (t == 0) {
                const int* ci = (const int*)captions;
                bool is64 = true;
                #pragma unroll
                for (int i = 1; i < 32; i += 2) if (ci[i]) is64 = false;
                tok = is64 ? (int)((const long long*)captions)[tid] : ci[tid];
            } else {
                ull pk = g_amax[(t + 1) & 1][tid];
                tok = (int)(0x7FFFFFFFu - (unsigned)(pk & 0xFFFFFFFFull));
            }
            stok[tid] = tok;
        }
        __syncthreads();

        // ---- ih GEMM: plane gid&1 ----
        {
            auto stage = [&](int buf, int c) {
                const int k0 = kbase + c * 64;
                uint32_t base = sb + buf * DSM_STRIDE;
                #pragma unroll
                for (int q = 0; q < 4; q++) {
                    int idx = tid + q * 256;
                    int r = idx >> 3, uu = idx & 7;
                    uint32_t dst = SW128((uint32_t)(r * 128 + uu * 16));
                    size_t so = (size_t)(rb + r) * 512 + k0 + uu * 8;
                    cpasync16(base + DSM_W1 + dst, g_Ib1 + so);
                    cpasync16(base + DSM_W2 + dst, g_Ib2 + so);
                }
                asm volatile("cp.async.commit_group;" ::: "memory");
                // gather embed rows, split fp32 -> bf16 hi/lo, STS
                #pragma unroll
                for (int q = 0; q < 4; q++) {
                    int idx = tid + q * 256;
                    int b = idx >> 4, kk = (idx & 15) * 4;
                    float4 x = *(const float4*)(embed + (size_t)stok[b] * E_ + k0 + kk);
                    __nv_bfloat16 hx = __float2bfloat16(x.x), hy = __float2bfloat16(x.y);
                    __nv_bfloat16 hz = __float2bfloat16(x.z), hw = __float2bfloat16(x.w);
                    __nv_bfloat162 hi0; hi0.x = hx; hi0.y = hy;
                    __nv_bfloat162 hi1; hi1.x = hz; hi1.y = hw;
                    __nv_bfloat162 lo0, lo1;
                    lo0.x = __float2bfloat16(x.x - __bfloat162float(hx));
                    lo0.y = __float2bfloat16(x.y - __bfloat162float(hy));
                    lo1.x = __float2bfloat16(x.z - __bfloat162float(hz));
                    lo1.y = __float2bfloat16(x.w - __bfloat162float(hw));
                    uint32_t dst = SW128((uint32_t)(b * 128 + kk * 2));
                    ull hp, lp;
                    memcpy(&hp, &hi0, 4); memcpy(((char*)&hp) + 4, &hi1, 4);
                    memcpy(&lp, &lo0, 4); memcpy(((char*)&lp) + 4, &lo1, 4);
                    *(ull*)(dsm + buf * DSM_STRIDE + DSM_H1 + dst) = hp;
                    *(ull*)(dsm + buf * DSM_STRIDE + DSM_H2 + dst) = lp;
                }
            };

            const int sel = lid >> 3, row = lid & 7;
            const int aV  = 16 * wid + ((sel & 1) << 3) + row;
            const int aKo = (sel >> 1) << 3;
            const int bB  = ((sel >> 1) << 3) + row;
            const int bKo = (sel & 1) << 3;

            float acc[8][4] = {};
            stage(0, 0);
            for (int c = 0; c < 4; c++) {
                if (c < 3) {
                    stage((c + 1) & 1, c + 1);
                    asm volatile("cp.async.wait_group 1;" ::: "memory");
                } else {
                    asm volatile("cp.async.wait_group 0;" ::: "memory");
                }
                __syncthreads();
                const uint32_t base = sb + (c & 1) * DSM_STRIDE;
                #pragma unroll
                for (int kk = 0; kk < 64; kk += 16) {
                    uint32_t a1[4], a2[4];
                    uint32_t aoff = SW128((uint32_t)(aV * 128 + (kk + aKo) * 2));
                    ldsm4(a1, base + DSM_W1 + aoff);
                    ldsm4(a2, base + DSM_W2 + aoff);
                    #pragma unroll
                    for (int jp = 0; jp < 4; jp++) {
                        uint32_t b1[4], b2[4];
                        uint32_t boff = SW128((uint32_t)((16 * jp + bB) * 128 + (kk + bKo) * 2));
                        ldsm4(b1, base + DSM_H1 + boff);
                        ldsm4(b2, base + DSM_H2 + boff);
                        mma16816(acc[2 * jp],     a1, b1[0], b1[1]);
                        mma16816(acc[2 * jp + 1], a1, b1[2], b1[3]);
                        mma16816(acc[2 * jp],     a1, b2[0], b2[1]);
                        mma16816(acc[2 * jp + 1], a1, b2[2], b2[3]);
                        mma16816(acc[2 * jp],     a2, b1[0], b1[1]);
                        mma16816(acc[2 * jp + 1], a2, b1[2], b1[3]);
                    }
                }
                __syncthreads();
            }

            float* gp = g_gates[gid & 1];
            const int qrow = lid >> 2, qcol = lid & 3;
            const int r0 = rb + 16 * wid + qrow;
            const int r1 = r0 + 8;
            #pragma unroll
            for (int j = 0; j < 8; j++) {
                int blo = 8 * j + 2 * qcol, bhi = blo + 1;
                gp[(size_t)blo * G4 + r0] = acc[j][0];
                gp[(size_t)bhi * G4 + r0] = acc[j][1];
                gp[(size_t)blo * G4 + r1] = acc[j][2];
                gp[(size_t)bhi * G4 + r1] = acc[j][3];
            }
        }

        __threadfence();
        bar_all(tid, &s_tk);          // barrier A: gates complete

        // ---- fused LSTM update: 32 blocks x 256 thr x 4 elems ----
        #pragma unroll
        for (int e = 0; e < 4; e++) {
            int idx = (gid * 256 + tid) * 4 + e;   // 0..32767
            int b = idx >> 9, j = idx & 511;
            const int base = b * G4;
            float z[4];
            #pragma unroll
            for (int g = 0; g < 4; g++) {
                int o = base + j + g * 512;
                z[g] = b_ih[j + g * 512] + b_hh[j + g * 512]
                     + __ldcg(&g_gates[0][o]) + __ldcg(&g_gates[1][o])
                     + __ldcg(&g_gates[2][o]) + __ldcg(&g_gates[3][o]);
            }
            float i_ = 1.0f / (1.0f + expf(-z[0]));
            float f_ = 1.0f / (1.0f + expf(-z[1]));
            float gg = tanhf(z[2]);
            float o_ = 1.0f / (1.0f + expf(-z[3]));
            float c_old = (t == 0) ? features[b * H_ + j] : g_c[b * H_ + j];
            float c_new = f_ * c_old + i_ * gg;
            float h_new = o_ * tanhf(c_new);
            g_c[b * H_ + j] = c_new;
            __nv_bfloat16 h1 = __float2bfloat16(h_new);
            g_hb[0][b * 512 + j] = h1;
            g_hb[1][b * 512 + j] = __float2bfloat16(h_new - __bfloat162float(h1));
        }

        __threadfence();
        bar_all(tid, &s_tk);          // barrier B: h(t) ready

        if (t < T_ - 1)
            gates_hh(dsm, sb, tid, wid, lid, rb, kbase, 2 + (gid & 1));
        return;
    }

    // ================= logits block =================
    if (tid < 64) s_amax[tid] = 0ull;
    if (t < 0) return;

    const int vb = bid * 128;

    // pre-stage W of chunk 0 (independent of h) — overlaps the gate phase
    {
        #pragma unroll
        for (int q = 0; q < 4; q++) {
            int idx = tid + q * 256;
            int v = idx >> 3, uu = idx & 7;
            uint32_t dst = SW128((uint32_t)(v * 128 + uu * 16));
            size_t so = (size_t)(vb + v) * 512 + uu * 8;
            cpasync16(sb + DSM_W1 + dst, g_Wb1 + so);
            cpasync16(sb + DSM_W2 + dst, g_Wb2 + so);
        }
        asm volatile("cp.async.commit_group;" ::: "memory");   // group 0
    }

    bar_all(tid, &s_tk);              // barrier A
    bar_all(tid, &s_tk);              // barrier B: h(t) splits ready

    if (bid == 0 && tid < 64) g_amax[(t + 1) & 1][tid] = 0ull;

    // stage H of chunk 0 (group 1), then full chunk 1 (group 2)
    {
        #pragma unroll
        for (int q = 0; q < 2; q++) {
            int idx = tid + q * 256;
            int b = idx >> 3, uu = idx & 7;
            uint32_t dst = SW128((uint32_t)(b * 128 + uu * 16));
            size_t so = (size_t)b * 512 + uu * 8;
            cpasync16(sb + DSM_H1 + dst, g_hb[0] + so);
            cpasync16(sb + DSM_H2 + dst, g_hb[1] + so);
        }
        asm volatile("cp.async.commit_group;" ::: "memory");   // group 1
    }
    stage_chunk(sb, 1, vb, 64, tid);                           // group 2

    const int sel = lid >> 3, row = lid & 7;
    const int aV  = 16 * wid + ((sel & 1) << 3) + row;
    const int aKo = (sel >> 1) << 3;
    const int bB  = ((sel >> 1) << 3) + row;
    const int bKo = (sel & 1) << 3;

    float acc[8][4] = {};

    for (int c = 0; c < 8; c++) {
        if (c >= 1 && c < 7) stage_chunk(sb, (c + 1) & 1, vb, (c + 1) * 64, tid);
        if (c < 7) { asm volatile("cp.async.wait_group 1;" ::: "memory"); }
        else       { asm volatile("cp.async.wait_group 0;" ::: "memory"); }
        __syncthreads();
        const uint32_t base = sb + (c & 1) * DSM_STRIDE;

        #pragma unroll
        for (int kk = 0; kk < 64; kk += 16) {
            uint32_t a1[4], a2[4];
            uint32_t aoff = SW128((uint32_t)(aV * 128 + (kk + aKo) * 2));
            ldsm4(a1, base + DSM_W1 + aoff);
            ldsm4(a2, base + DSM_W2 + aoff);
            #pragma unroll
            for (int jp = 0; jp < 4; jp++) {
                uint32_t b1[4], b2[4];
                uint32_t boff = SW128((uint32_t)((16 * jp + bB) * 128 + (kk + bKo) * 2));
                ldsm4(b1, base + DSM_H1 + boff);
                ldsm4(b2, base + DSM_H2 + boff);
                mma16816(acc[2 * jp],     a1, b1[0], b1[1]);
                mma16816(acc[2 * jp + 1], a1, b1[2], b1[3]);
                mma16816(acc[2 * jp],     a1, b2[0], b2[1]);
                mma16816(acc[2 * jp + 1], a1, b2[2], b2[3]);
                mma16816(acc[2 * jp],     a2, b1[0], b1[1]);
                mma16816(acc[2 * jp + 1], a2, b1[2], b1[3]);
            }
        }
        __syncthreads();
    }

    // epilogue: bias, store, argmax
    const int qrow = lid >> 2, qcol = lid & 3;
    const int v0 = vb + 16 * wid + qrow;
    const int v1 = v0 + 8;
    const float bi0 = lin_b[v0], bi1 = lin_b[v1];

    #pragma unroll
    for (int j = 0; j < 8; j++) {
        int blo = 8 * j + 2 * qcol, bhi = blo + 1;
        float c0 = acc[j][0] + bi0;
        float c1 = acc[j][1] + bi0;
        float c2 = acc[j][2] + bi1;
        float c3 = acc[j][3] + bi1;
        out[((size_t)blo * T_ + t) * V_ + v0] = c0;
        out[((size_t)bhi * T_ + t) * V_ + v0] = c1;
        out[((size_t)blo * T_ + t) * V_ + v1] = c2;
        out[((size_t)bhi * T_ + t) * V_ + v1] = c3;

        ull klo = ((ull)fkey(c0) << 32) | (ull)(0x7FFFFFFFu - (unsigned)v0);
        ull k2  = ((ull)fkey(c2) << 32) | (ull)(0x7FFFFFFFu - (unsigned)v1);
        if (k2 > klo) klo = k2;
        ull khi = ((ull)fkey(c1) << 32) | (ull)(0x7FFFFFFFu - (unsigned)v0);
        k2      = ((ull)fkey(c3) << 32) | (ull)(0x7FFFFFFFu - (unsigned)v1);
        if (k2 > khi) khi = k2;
        #pragma unroll
        for (int s = 4; s < 32; s <<= 1) {
            ull o1 = __shfl_xor_sync(0xFFFFFFFFu, klo, s); if (o1 > klo) klo = o1;
            ull o2 = __shfl_xor_sync(0xFFFFFFFFu, khi, s); if (o2 > khi) khi = o2;
        }
        if (lid < 4) {
            atomicMax(&s_amax[blo], klo);
            atomicMax(&s_amax[bhi], khi);
        }
    }
    __syncthreads();
    if (tid < 64) atomicMax(&g_amax[t & 1][tid], s_amax[tid]);
}

// =========================================================
extern "C" void kernel_launch(void* const* d_in, const int* in_sizes, int n_in,
                              void* d_out, int out_size)
{
    const float* features = (const float*)d_in[0];
    const void*  captions = d_in[1];
    int off = (in_sizes[2] == V_ * E_) ? 0 : 1;   // 'lengths' may be materialized
    const float* embed = (const float*)d_in[2 + off];
    const float* W_ih  = (const float*)d_in[3 + off];
    const float* W_hh  = (const float*)d_in[4 + off];
    const float* b_ih  = (const float*)d_in[5 + off];
    const float* b_hh  = (const float*)d_in[6 + off];
    const float* lin_W = (const float*)d_in[7 + off];
    const float* lin_b = (const float*)d_in[8 + off];
    float* out = (float*)d_out;
    (void)n_in; (void)out_size;

    cudaFuncSetAttribute(k_step, cudaFuncAttributeMaxDynamicSharedMemorySize, DSM_TOT);

    // prologue: all bf16 splits, then hh plane for t=0 (h(-1)=features; no barriers)
    k_splitall<<<72320, 256>>>(lin_W, W_ih, W_hh, features);
    k_step<<<NB, 256, DSM_TOT>>>(-1, captions, embed, features, b_ih, b_hh, lin_b, out);

    for (int t = 0; t < T_; t++)
        k_step<<<NB, 256, DSM_TOT>>>(t, captions, embed, features, b_ih, b_hh, lin_b, out);
}

// round 16
// speedup vs baseline: 1.2341x; 1.2341x over previous
#include <cuda_runtime.h>
#include <cuda_bf16.h>
#include <math.h>
#include <stdint.h>

#define B_  64
#define E_  512
#define H_  512
#define V_  32000
#define T_  32
#define G4  2048   // 4*H

typedef unsigned long long ull;

// ---------------- persistent device state ----------------
__device__ __align__(16) float g_h[2][B_ * H_];     // double-buffered hidden state
__device__ __align__(16) float g_c[B_ * H_];        // cell state
__device__ __align__(16) float g_gates[4][B_ * G4]; // planes: ih-k0, ih-k1, hh-k0, hh-k1
__device__ ull g_amax[2][B_];                       // packed argmax accumulators
// bf16 2-term splits
__device__ __align__(16) __nv_bfloat16 g_Wb1[(size_t)V_ * 512];   // lin_W hi
__device__ __align__(16) __nv_bfloat16 g_Wb2[(size_t)V_ * 512];   // lin_W lo
__device__ __align__(16) __nv_bfloat16 g_Ib1[2048 * 512];         // W_ih hi
__device__ __align__(16) __nv_bfloat16 g_Ib2[2048 * 512];         // W_ih lo
__device__ __align__(16) __nv_bfloat16 g_Hb1[2048 * 512];         // W_hh hi
__device__ __align__(16) __nv_bfloat16 g_Hb2[2048 * 512];         // W_hh lo
__device__ __align__(16) __nv_bfloat16 g_hb[2][B_ * 512];         // h(t) splits [term][b*512+k]

__device__ __forceinline__ unsigned fkey(float f) {
    unsigned u = __float_as_uint(f);
    return (u & 0x80000000u) ? ~u : (u | 0x80000000u);
}
__device__ __forceinline__ uint32_t smem_u32(const void* p) {
    uint32_t a;
    asm("{ .reg .u64 t; cvta.to.shared.u64 t, %1; cvt.u32.u64 %0, t; }" : "=r"(a) : "l"(p));
    return a;
}
__device__ __forceinline__ void ldsm4(uint32_t* r, uint32_t addr) {
    asm volatile("ldmatrix.sync.aligned.m8n8.x4.shared.b16 {%0,%1,%2,%3}, [%4];"
        : "=r"(r[0]), "=r"(r[1]), "=r"(r[2]), "=r"(r[3]) : "r"(addr));
}
__device__ __forceinline__ void mma16816(float* d, const uint32_t* a, uint32_t b0, uint32_t b1) {
    asm volatile("mma.sync.aligned.m16n8k16.row.col.f32.bf16.bf16.f32 "
        "{%0,%1,%2,%3}, {%4,%5,%6,%7}, {%8,%9}, {%0,%1,%2,%3};"
        : "+f"(d[0]), "+f"(d[1]), "+f"(d[2]), "+f"(d[3])
        : "r"(a[0]), "r"(a[1]), "r"(a[2]), "r"(a[3]), "r"(b0), "r"(b1));
}
__device__ __forceinline__ void cpasync16(uint32_t dst, const void* src) {
    asm volatile("cp.async.cg.shared.global [%0], [%1], 16;" :: "r"(dst), "l"(src));
}
#define SW128(o) ((o) ^ (((o) >> 3) & 0x70))

// Dynamic smem layout (per buffer): W1 16K | W2 16K | H1 8K | H2 8K
#define DSM_STRIDE 49152
#define DSM_W1 0
#define DSM_W2 16384
#define DSM_H1 32768
#define DSM_H2 40960
#define DSM_TOT (2 * DSM_STRIDE)

// =========================================================
// k_splitall: one prologue kernel producing every bf16 split.
// =========================================================
__global__ __launch_bounds__(256) void k_splitall(
    const float* __restrict__ lin_W, const float* __restrict__ W_ih,
    const float* __restrict__ W_hh,  const float* __restrict__ features)
{
    const int bid = blockIdx.x;
    const int tid = threadIdx.x;
    if (bid < 64000) {
        size_t i = (size_t)bid * 256 + tid;
        float w = lin_W[i];
        __nv_bfloat16 h1 = __float2bfloat16(w);
        g_Wb1[i] = h1;
        g_Wb2[i] = __float2bfloat16(w - __bfloat162float(h1));
    } else if (bid < 68096) {
        int i = (bid - 64000) * 256 + tid;
        float w = W_ih[i];
        __nv_bfloat16 h1 = __float2bfloat16(w);
        g_Ib1[i] = h1;
        g_Ib2[i] = __float2bfloat16(w - __bfloat162float(h1));
    } else if (bid < 72192) {
        int i = (bid - 68096) * 256 + tid;
        float w = W_hh[i];
        __nv_bfloat16 h1 = __float2bfloat16(w);
        g_Hb1[i] = h1;
        g_Hb2[i] = __float2bfloat16(w - __bfloat162float(h1));
    } else {
        int i = (bid - 72192) * 256 + tid;
        float f = features[i];
        __nv_bfloat16 h1 = __float2bfloat16(f);
        g_hb[0][i] = h1;
        g_hb[1][i] = __float2bfloat16(f - __bfloat162float(h1));
    }
}

// =========================================================
// k_prep: gate pre-activation partials via HMMA 3-pass bf16 split.
// grid 64: bid -> wsel = bid>>5 (0: W_ih@x, 1: W_hh@h), sub = bid&31,
//   rblk = sub>>1 (128-row block of 2048), khalf = sub&1 (256-k half).
// Output plane = wsel*2 + khalf. Block tile 128r x 64b x 256k (4 chunks of 64k).
// =========================================================
__global__ __launch_bounds__(256) void k_prep(
    int t, const void* __restrict__ captions, const float* __restrict__ embed)
{
    extern __shared__ char dsm[];
    __shared__ int stok[B_];
    const uint32_t sb = smem_u32(dsm);
    const int tid = threadIdx.x;
    const int bid = blockIdx.x;
    const int wid = tid >> 5, lid = tid & 31;

    const int wsel  = bid >> 5;
    const int sub   = bid & 31;
    const int rb    = (sub >> 1) * 128;
    const int kbase = (sub & 1) * 256;

    if (t == 0 && bid == 0 && tid < 128)
        g_amax[tid >> 6][tid & 63] = 0ull;

    if (wsel == 0 && tid < B_) {
        int tok;
        if (t == 0) {
            const int* ci = (const int*)captions;
            bool is64 = true;
            #pragma unroll
            for (int i = 1; i < 32; i += 2) if (ci[i]) is64 = false;
            tok = is64 ? (int)((const long long*)captions)[tid] : ci[tid];
        } else {
            ull pk = g_amax[(t + 1) & 1][tid];
            tok = (int)(0x7FFFFFFFu - (unsigned)(pk & 0xFFFFFFFFull));
        }
        stok[tid] = tok;
    }
    __syncthreads();

    const __nv_bfloat16* A1 = wsel ? g_Hb1 : g_Ib1;
    const __nv_bfloat16* A2 = wsel ? g_Hb2 : g_Ib2;

    // ---- staging ----
    auto stage = [&](int buf, int c) {
        const int k0 = kbase + c * 64;
        uint32_t base = sb + buf * DSM_STRIDE;
        #pragma unroll
        for (int q = 0; q < 4; q++) {
            int idx = tid + q * 256;
            int r = idx >> 3, uu = idx & 7;
            uint32_t dst = SW128((uint32_t)(r * 128 + uu * 16));
            size_t so = (size_t)(rb + r) * 512 + k0 + uu * 8;
            cpasync16(base + DSM_W1 + dst, A1 + so);
            cpasync16(base + DSM_W2 + dst, A2 + so);
        }
        if (wsel) {
            #pragma unroll
            for (int q = 0; q < 2; q++) {
                int idx = tid + q * 256;
                int b = idx >> 3, uu = idx & 7;
                uint32_t dst = SW128((uint32_t)(b * 128 + uu * 16));
                size_t so = (size_t)b * 512 + k0 + uu * 8;
                cpasync16(base + DSM_H1 + dst, g_hb[0] + so);
                cpasync16(base + DSM_H2 + dst, g_hb[1] + so);
            }
            asm volatile("cp.async.commit_group;" ::: "memory");
        } else {
            asm volatile("cp.async.commit_group;" ::: "memory");
            // gather embed rows, split fp32 -> bf16 hi/lo, STS
            #pragma unroll
            for (int q = 0; q < 4; q++) {
                int idx = tid + q * 256;
                int b = idx >> 4, kk = (idx & 15) * 4;
                float4 x = *(const float4*)(embed + (size_t)stok[b] * E_ + k0 + kk);
                __nv_bfloat16 hx = __float2bfloat16(x.x), hy = __float2bfloat16(x.y);
                __nv_bfloat16 hz = __float2bfloat16(x.z), hw = __float2bfloat16(x.w);
                __nv_bfloat162 hi0; hi0.x = hx; hi0.y = hy;
                __nv_bfloat162 hi1; hi1.x = hz; hi1.y = hw;
                __nv_bfloat162 lo0, lo1;
                lo0.x = __float2bfloat16(x.x - __bfloat162float(hx));
                lo0.y = __float2bfloat16(x.y - __bfloat162float(hy));
                lo1.x = __float2bfloat16(x.z - __bfloat162float(hz));
                lo1.y = __float2bfloat16(x.w - __bfloat162float(hw));
                uint32_t dst = SW128((uint32_t)(b * 128 + kk * 2));
                ull hp, lp;
                memcpy(&hp, &hi0, 4); memcpy(((char*)&hp) + 4, &hi1, 4);
                memcpy(&lp, &lo0, 4); memcpy(((char*)&lp) + 4, &lo1, 4);
                *(ull*)(dsm + buf * DSM_STRIDE + DSM_H1 + dst) = hp;
                *(ull*)(dsm + buf * DSM_STRIDE + DSM_H2 + dst) = lp;
            }
        }
    };

    // lane-role constants
    const int sel = lid >> 3, row = lid & 7;
    const int aV  = 16 * wid + ((sel & 1) << 3) + row;
    const int aKo = (sel >> 1) << 3;
    const int bB  = ((sel >> 1) << 3) + row;
    const int bKo = (sel & 1) << 3;

    float acc[8][4] = {};

    stage(0, 0);
    for (int c = 0; c < 4; c++) {
        if (c < 3) {
            stage((c + 1) & 1, c + 1);
            asm volatile("cp.async.wait_group 1;" ::: "memory");
        } else {
            asm volatile("cp.async.wait_group 0;" ::: "memory");
        }
        __syncthreads();
        const uint32_t base = sb + (c & 1) * DSM_STRIDE;

        #pragma unroll
        for (int kk = 0; kk < 64; kk += 16) {
            uint32_t a1[4], a2[4];
            uint32_t aoff = SW128((uint32_t)(aV * 128 + (kk + aKo) * 2));
            ldsm4(a1, base + DSM_W1 + aoff);
            ldsm4(a2, base + DSM_W2 + aoff);
            #pragma unroll
            for (int jp = 0; jp < 4; jp++) {
                uint32_t b1[4], b2[4];
                uint32_t boff = SW128((uint32_t)((16 * jp + bB) * 128 + (kk + bKo) * 2));
                ldsm4(b1, base + DSM_H1 + boff);
                ldsm4(b2, base + DSM_H2 + boff);
                mma16816(acc[2 * jp],     a1, b1[0], b1[1]);
                mma16816(acc[2 * jp + 1], a1, b1[2], b1[3]);
                mma16816(acc[2 * jp],     a1, b2[0], b2[1]);
                mma16816(acc[2 * jp + 1], a1, b2[2], b2[3]);
                mma16816(acc[2 * jp],     a2, b1[0], b1[1]);
                mma16816(acc[2 * jp + 1], a2, b1[2], b1[3]);
            }
        }
        __syncthreads();
    }

    // epilogue: write fp32 partials into plane
    float* gp = g_gates[wsel * 2 + (sub & 1)];
    const int qrow = lid >> 2, qcol = lid & 3;
    const int r0 = rb + 16 * wid + qrow;
    const int r1 = r0 + 8;
    #pragma unroll
    for (int j = 0; j < 8; j++) {
        int blo = 8 * j + 2 * qcol, bhi = blo + 1;
        gp[(size_t)blo * G4 + r0] = acc[j][0];
        gp[(size_t)bhi * G4 + r0] = acc[j][1];
        gp[(size_t)blo * G4 + r1] = acc[j][2];
        gp[(size_t)bhi * G4 + r1] = acc[j][3];
    }
}

// =========================================================
// k_update: sum 4 planes + biases, LSTM nonlin, write h + bf16 splits.
// =========================================================
__global__ __launch_bounds__(256) void k_update(
    int t, const float* __restrict__ features,
    const float* __restrict__ b_ih, const float* __restrict__ b_hh)
{
    int idx = blockIdx.x * 256 + threadIdx.x;
    int b = idx >> 9, j = idx & 511;
    const int base = b * G4;

    float z[4];
    #pragma unroll
    for (int g = 0; g < 4; g++) {
        int o = base + j + g * 512;
        z[g] = b_ih[j + g * 512] + b_hh[j + g * 512]
             + g_gates[0][o] + g_gates[1][o] + g_gates[2][o] + g_gates[3][o];
    }
    float i_ = 1.0f / (1.0f + expf(-z[0]));
    float f_ = 1.0f / (1.0f + expf(-z[1]));
    float gg = tanhf(z[2]);
    float o_ = 1.0f / (1.0f + expf(-z[3]));

    float c_old = (t == 0) ? features[b * H_ + j] : g_c[b * H_ + j];
    float c_new = f_ * c_old + i_ * gg;
    float h_new = o_ * tanhf(c_new);

    g_c[b * H_ + j]        = c_new;
    g_h[t & 1][b * H_ + j] = h_new;

    __nv_bfloat16 h1 = __float2bfloat16(h_new);
    g_hb[0][b * 512 + j] = h1;
    g_hb[1][b * 512 + j] = __float2bfloat16(h_new - __bfloat162float(h1));
}

// =========================================================
// k_big: logits via HMMA bf16 3-pass split. grid 250, 512 threads.
// Block: 128v x 64b x 512k (8 chunks of 64k), double-buffered cp.async.
// Warp w: mt = w&7 (m16 v-tile), nh = w>>3 (32-batch half). 32 warps/SM.
// =========================================================
__device__ __forceinline__ void stage_chunk(uint32_t sb, int buf, int vb, int k0, int tid)
{
    uint32_t base = sb + buf * DSM_STRIDE;
    #pragma unroll
    for (int q = 0; q < 2; q++) {
        int idx = tid + q * 512;          // 0..1023
        int v = idx >> 3, uu = idx & 7;
        uint32_t dst = SW128((uint32_t)(v * 128 + uu * 16));
        size_t so = (size_t)(vb + v) * 512 + k0 + uu * 8;
        cpasync16(base + DSM_W1 + dst, g_Wb1 + so);
        cpasync16(base + DSM_W2 + dst, g_Wb2 + so);
    }
    {
        int b = tid >> 3, uu = tid & 7;   // 0..511 covers 64b x 8uu
        uint32_t dst = SW128((uint32_t)(b * 128 + uu * 16));
        size_t so = (size_t)b * 512 + k0 + uu * 8;
        cpasync16(base + DSM_H1 + dst, g_hb[0] + so);
        cpasync16(base + DSM_H2 + dst, g_hb[1] + so);
    }
    asm volatile("cp.async.commit_group;" ::: "memory");
}

__global__ __launch_bounds__(512, 2) void k_big(
    int t, const float* __restrict__ lin_b, float* __restrict__ out)
{
    extern __shared__ char dsm[];
    __shared__ ull s_amax[64];
    const uint32_t sb = smem_u32(dsm);
    const int tid = threadIdx.x;
    const int bid = blockIdx.x;
    const int wid = tid >> 5, lid = tid & 31;
    const int vb = bid * 128;

    if (tid < 64) s_amax[tid] = 0ull;
    if (bid == 0 && tid < 64) g_amax[(t + 1) & 1][tid] = 0ull;

    const int mt = wid & 7;         // m16 tile (v rows 16*mt..)
    const int nh = wid >> 3;        // batch half (b 32*nh..)
    const int sel = lid >> 3, row = lid & 7;
    const int aV  = 16 * mt + ((sel & 1) << 3) + row;
    const int aKo = (sel >> 1) << 3;
    const int bB  = 32 * nh + ((sel >> 1) << 3) + row;
    const int bKo = (sel & 1) << 3;

    float acc[4][4] = {};           // [jp*2 + n8half][quad]

    stage_chunk(sb, 0, vb, 0, tid);
    for (int c = 0; c < 8; c++) {
        if (c < 7) {
            stage_chunk(sb, (c + 1) & 1, vb, (c + 1) * 64, tid);
            asm volatile("cp.async.wait_group 1;" ::: "memory");
        } else {
            asm volatile("cp.async.wait_group 0;" ::: "memory");
        }
        __syncthreads();
        const uint32_t base = sb + (c & 1) * DSM_STRIDE;

        #pragma unroll
        for (int kk = 0; kk < 64; kk += 16) {
            uint32_t a1[4], a2[4];
            uint32_t aoff = SW128((uint32_t)(aV * 128 + (kk + aKo) * 2));
            ldsm4(a1, base + DSM_W1 + aoff);
            ldsm4(a2, base + DSM_W2 + aoff);
            #pragma unroll
            for (int jp = 0; jp < 2; jp++) {
                uint32_t b1[4], b2[4];
                uint32_t boff = SW128((uint32_t)((16 * jp + bB) * 128 + (kk + bKo) * 2));
                ldsm4(b1, base + DSM_H1 + boff);
                ldsm4(b2, base + DSM_H2 + boff);
                mma16816(acc[2 * jp],     a1, b1[0], b1[1]);
                mma16816(acc[2 * jp + 1], a1, b1[2], b1[3]);
                mma16816(acc[2 * jp],     a1, b2[0], b2[1]);
                mma16816(acc[2 * jp + 1], a1, b2[2], b2[3]);
                mma16816(acc[2 * jp],     a2, b1[0], b1[1]);
                mma16816(acc[2 * jp + 1], a2, b1[2], b1[3]);
            }
        }
        __syncthreads();
    }

    // epilogue: bias, store, argmax
    const int qrow = lid >> 2, qcol = lid & 3;
    const int v0 = vb + 16 * mt + qrow;
    const int v1 = v0 + 8;
    const float bi0 = lin_b[v0], bi1 = lin_b[v1];

    #pragma unroll
    for (int j = 0; j < 4; j++) {           // j = jp*2 + n8half
        int blo = 32 * nh + 8 * j + 2 * qcol, bhi = blo + 1;
        float c0 = acc[j][0] + bi0;
        float c1 = acc[j][1] + bi0;
        float c2 = acc[j][2] + bi1;
        float c3 = acc[j][3] + bi1;
        out[((size_t)blo * T_ + t) * V_ + v0] = c0;
        out[((size_t)bhi * T_ + t) * V_ + v0] = c1;
        out[((size_t)blo * T_ + t) * V_ + v1] = c2;
        out[((size_t)bhi * T_ + t) * V_ + v1] = c3;

        ull klo = ((ull)fkey(c0) << 32) | (ull)(0x7FFFFFFFu - (unsigned)v0);
        ull k2  = ((ull)fkey(c2) << 32) | (ull)(0x7FFFFFFFu - (unsigned)v1);
        if (k2 > klo) klo = k2;
        ull khi = ((ull)fkey(c1) << 32) | (ull)(0x7FFFFFFFu - (unsigned)v0);
        k2      = ((ull)fkey(c3) << 32) | (ull)(0x7FFFFFFFu - (unsigned)v1);
        if (k2 > khi) khi = k2;
        #pragma unroll
        for (int s = 4; s < 32; s <<= 1) {  // reduce over qrow lanes
            ull o1 = __shfl_xor_sync(0xFFFFFFFFu, klo, s); if (o1 > klo) klo = o1;
            ull o2 = __shfl_xor_sync(0xFFFFFFFFu, khi, s); if (o2 > khi) khi = o2;
        }
        if (lid < 4) {
            atomicMax(&s_amax[blo], klo);
            atomicMax(&s_amax[bhi], khi);
        }
    }
    __syncthreads();
    if (tid < 64) atomicMax(&g_amax[t & 1][tid], s_amax[tid]);
}

// =========================================================
extern "C" void kernel_launch(void* const* d_in, const int* in_sizes, int n_in,
                              void* d_out, int out_size)
{
    const float* features = (const float*)d_in[0];
    const void*  captions = d_in[1];
    int off = (in_sizes[2] == V_ * E_) ? 0 : 1;   // 'lengths' may be materialized
    const float* embed = (const float*)d_in[2 + off];
    const float* W_ih  = (const float*)d_in[3 + off];
    const float* W_hh  = (const float*)d_in[4 + off];
    const float* b_ih  = (const float*)d_in[5 + off];
    const float* b_hh  = (const float*)d_in[6 + off];
    const float* lin_W = (const float*)d_in[7 + off];
    const float* lin_b = (const float*)d_in[8 + off];
    float* out = (float*)d_out;
    (void)n_in; (void)out_size;

    cudaFuncSetAttribute(k_big,  cudaFuncAttributeMaxDynamicSharedMemorySize, DSM_TOT);
    cudaFuncSetAttribute(k_prep, cudaFuncAttributeMaxDynamicSharedMemorySize, DSM_TOT);

    // one-time prologue: all bf16 splits (weights + h(-1)=features)
    k_splitall<<<72320, 256>>>(lin_W, W_ih, W_hh, features);

    for (int t = 0; t < T_; t++) {
        k_prep<<<64, 256, DSM_TOT>>>(t, captions, embed);
        k_update<<<128, 256>>>(t, features, b_ih, b_hh);
        k_big<<<250, 512, DSM_TOT>>>(t, lin_b, out);
    }
}